// round 1
// baseline (speedup 1.0000x reference)
#include <cuda_runtime.h>
#include <cuda_bf16.h>
#include <float.h>
#include <math.h>

// Problem constants (fixed shapes)
#define BN_TOT 64      // b*r
#define NB 2           // b
#define RR 32          // r (tie_attn_dim)
#define NN 512         // n (sequence)
#define DIMC 256       // DIM
#define HH 8           // heads
#define DH 64          // dim_head
#define INNERD 512     // HH*DH
#define KW 15          // conv kernel

// ---------------- scratch (device globals; no allocations allowed) ----------
__device__ float g_hdw[BN_TOT * NN * DIMC];        // conv output, (bn, i, c)
__device__ float g_qpre[BN_TOT * NN * INNERD];     // q before rotary, (bn, i, hd)
__device__ float g_kv[BN_TOT * NN * 2 * INNERD];   // k|v, (bn, i, 2*inner)
__device__ float g_qr[NB * HH * NN * RR * DH];     // (b,h,i, r*64+d)
__device__ float g_kr[NB * HH * NN * RR * DH];
__device__ float g_dots[NB * HH * NN * NN];        // (b,h,i,j)
__device__ float g_oi[BN_TOT * NN * INNERD];       // attn@v, (bn, i, h*64+d)
__device__ unsigned char g_mask[BN_TOT * NN];
__device__ float g_has_rows[BN_TOT];
__device__ float g_m_any[NB * NN];
__device__ float g_num_rows[NB];
__device__ int g_mask_mode;

// ---------------- mask dtype autodetect ------------------------------------
// mask may arrive as bool(u8), int32, or float32. Only the first 32768 bytes
// are guaranteed to exist under every interpretation, so detect from those.
__global__ void k_detect(const unsigned char* m) {
    __shared__ int s_high, s_odd;
    if (threadIdx.x == 0) { s_high = 0; s_odd = 0; }
    __syncthreads();
    for (int idx = threadIdx.x; idx < BN_TOT * NN; idx += blockDim.x) {
        unsigned char v = m[idx];
        if (v > 1) s_high = 1;                 // 0x80 / 0x3F bytes of float 1.0f
        if ((idx & 3) && v) s_odd = 1;         // non-word-aligned nonzero => u8 bool
    }
    __syncthreads();
    if (threadIdx.x == 0) g_mask_mode = s_high ? 2 : (s_odd ? 0 : 1);
}

__global__ void k_norm_mask(const void* m) {
    int idx = blockIdx.x * blockDim.x + threadIdx.x;
    if (idx >= BN_TOT * NN) return;
    int mode = g_mask_mode;
    unsigned char v;
    if (mode == 0)      v = (((const unsigned char*)m)[idx] != 0);
    else if (mode == 1) v = (((const int*)m)[idx] != 0);
    else                v = (((const float*)m)[idx] != 0.0f);
    g_mask[idx] = v;
}

__global__ void k_hasrows() {          // 64 blocks x 256 thr
    int bn = blockIdx.x;
    int any = 0;
    for (int j = threadIdx.x; j < NN; j += blockDim.x) any |= g_mask[bn * NN + j];
    __shared__ int s;
    if (threadIdx.x == 0) s = 0;
    __syncthreads();
    if (any) s = 1;
    __syncthreads();
    if (threadIdx.x == 0) g_has_rows[bn] = (float)s;
}

__global__ void k_many() {             // 2 blocks x 512 thr
    int b = blockIdx.x;
    int i = threadIdx.x;
    int any = 0;
    for (int r = 0; r < RR; r++) any |= g_mask[(b * RR + r) * NN + i];
    g_m_any[b * NN + i] = (float)any;
    if (i == 0) {
        float s = 0.f;
        for (int r = 0; r < RR; r++) s += g_has_rows[b * RR + r];
        g_num_rows[b] = s;
    }
}

// ---------------- depthwise conv (k=15, same padding) -----------------------
__global__ void k_conv(const float* __restrict__ x,
                       const float* __restrict__ dww,
                       const float* __restrict__ dwb) {
    int bn = blockIdx.x >> 9;
    int i  = blockIdx.x & 511;
    int c  = threadIdx.x;
    float acc = dwb[c];
    const float* xr = x + (size_t)bn * NN * DIMC + c;
#pragma unroll
    for (int k = 0; k < KW; k++) {
        int ii = i + k - KW / 2;
        if (ii >= 0 && ii < NN) acc += xr[(size_t)ii * DIMC] * dww[c * KW + k];
    }
    g_hdw[((size_t)bn * NN + i) * DIMC + c] = acc;
}

// ---------------- generic tiled fp32 GEMM body -------------------------------
// C[m,n] = alpha * sum_k A[m,k]*Bop[k,n] (+ bias[n]).  Exact tiling assumed.
// BT=true:  B is (N,K) row-major K-contig (NT).  BT=false: B is (K,N) N-contig (NN).
template <int BM, int BNt, int BK, int TM, int TN, bool BT>
__device__ __forceinline__ void gemm_body(const float* __restrict__ A, int lda,
                                          const float* __restrict__ B, int ldb,
                                          float* __restrict__ C, int ldc,
                                          int K, const float* __restrict__ bias,
                                          float alpha, int bx, int by) {
    constexpr int TX = BNt / TN;
    constexpr int TY = BM / TM;
    constexpr int NT = TX * TY;
    __shared__ float As[BK][BM];
    __shared__ float Bs[BK][BNt];
    int tid = threadIdx.x;
    int tx = tid % TX, ty = tid / TX;
    float acc[TM][TN];
#pragma unroll
    for (int i = 0; i < TM; i++)
#pragma unroll
        for (int j = 0; j < TN; j++) acc[i][j] = 0.f;

    const float* Ab = A + (size_t)by * BM * lda;
    for (int k0 = 0; k0 < K; k0 += BK) {
#pragma unroll
        for (int idx = tid; idx < BM * BK; idx += NT) {
            int m = idx / BK, k = idx % BK;
            As[k][m] = Ab[(size_t)m * lda + k0 + k];
        }
        if (BT) {
#pragma unroll
            for (int idx = tid; idx < BNt * BK; idx += NT) {
                int n = idx / BK, k = idx % BK;
                Bs[k][n] = B[(size_t)(bx * BNt + n) * ldb + k0 + k];
            }
        } else {
#pragma unroll
            for (int idx = tid; idx < BNt * BK; idx += NT) {
                int k = idx / BNt, n = idx % BNt;
                Bs[k][n] = B[(size_t)(k0 + k) * ldb + bx * BNt + n];
            }
        }
        __syncthreads();
#pragma unroll
        for (int k = 0; k < BK; k++) {
            float ra[TM], rb[TN];
#pragma unroll
            for (int i = 0; i < TM; i++) ra[i] = As[k][ty * TM + i];
#pragma unroll
            for (int j = 0; j < TN; j++) rb[j] = Bs[k][tx * TN + j];
#pragma unroll
            for (int i = 0; i < TM; i++)
#pragma unroll
                for (int j = 0; j < TN; j++) acc[i][j] += ra[i] * rb[j];
        }
        __syncthreads();
    }
#pragma unroll
    for (int i = 0; i < TM; i++) {
        size_t m = (size_t)by * BM + ty * TM + i;
#pragma unroll
        for (int j = 0; j < TN; j++) {
            int n = bx * BNt + tx * TN + j;
            float v = acc[i][j] * alpha;
            if (bias) v += bias[n];
            C[m * ldc + n] = v;
        }
    }
}

// q = hdw @ pw_w^T + pw_b   (M=32768, N=512, K=256, NT)
__global__ void k_qproj(const float* __restrict__ pww, const float* __restrict__ pwb) {
    gemm_body<128, 128, 16, 8, 8, true>(g_hdw, DIMC, pww, DIMC, g_qpre, INNERD,
                                        DIMC, pwb, 1.f, blockIdx.x, blockIdx.y);
}

// kv = x @ w_kv            (M=32768, N=1024, K=256, NN)
__global__ void k_kvproj(const float* __restrict__ x, const float* __restrict__ wkv) {
    gemm_body<128, 128, 16, 8, 8, false>(x, DIMC, wkv, 2 * INNERD, g_kv, 2 * INNERD,
                                         DIMC, nullptr, 1.f, blockIdx.x, blockIdx.y);
}

// rotary on q (with has_rows zeroing) and k; relayout to (b,h,i, r*64+d)
__global__ void k_rotary() {
    size_t t = (size_t)blockIdx.x * blockDim.x + threadIdx.x;  // 64*512*512
    int hd = t & 511;
    int i  = (t >> 9) & 511;
    int bn = (int)(t >> 18);
    int d = hd & 63, h = hd >> 6;
    int j = d >> 1;
    float inv = powf(10000.0f, -(float)(2 * j) / 64.0f);
    float ang = (float)i * inv;
    float s = sinf(ang), c = cosf(ang);

    size_t src = ((size_t)bn * NN + i) * INNERD + hd;
    float qv = g_qpre[src];
    float qp = g_qpre[src ^ 1];
    float qo = (d & 1) ? (qv * c + qp * s) : (qv * c - qp * s);
    qo *= g_has_rows[bn];

    size_t srck = ((size_t)bn * NN + i) * (2 * INNERD) + hd;
    float kvv = g_kv[srck];
    float kp  = g_kv[srck ^ 1];
    float ko = (d & 1) ? (kvv * c + kp * s) : (kvv * c - kp * s);

    int b = bn >> 5, r = bn & 31;
    size_t dst = (((size_t)(b * HH + h) * NN + i) * (RR * DH)) + r * DH + d;
    g_qr[dst] = qo;
    g_kr[dst] = ko;
}

// dots[b,h] = alpha * Qr @ Kr^T   (16 batches, M=N=512, K=2048, NT)
__global__ void k_dots() {
    int bh = blockIdx.z;
    int b = bh >> 3;
    float alpha = 0.125f * rsqrtf(g_num_rows[b]);  // d^-0.5 * num_rows^-0.5
    const float* A = g_qr + (size_t)bh * NN * RR * DH;
    const float* B = g_kr + (size_t)bh * NN * RR * DH;
    float* C = g_dots + (size_t)bh * NN * NN;
    gemm_body<128, 128, 16, 8, 8, true>(A, RR * DH, B, RR * DH, C, NN,
                                        RR * DH, nullptr, alpha, blockIdx.x, blockIdx.y);
}

// masked softmax over j, in place. 8192 rows.
__global__ void k_softmax() {
    int row = blockIdx.x;          // (b*8+h)*512 + i
    int b = row >> 12;
    int i = row & 511;
    float* p = g_dots + (size_t)row * NN;
    float rv = g_m_any[b * NN + i];
    int t = threadIdx.x;

    float m0 = g_m_any[b * NN + t];
    float m1 = g_m_any[b * NN + t + 256];
    float x0 = (rv != 0.f && m0 != 0.f) ? p[t]       : -FLT_MAX;
    float x1 = (rv != 0.f && m1 != 0.f) ? p[t + 256] : -FLT_MAX;

    __shared__ float red[256];
    float mx = fmaxf(x0, x1);
    red[t] = mx;
    __syncthreads();
    for (int s = 128; s > 0; s >>= 1) {
        if (t < s) red[t] = fmaxf(red[t], red[t + s]);
        __syncthreads();
    }
    mx = red[0];
    __syncthreads();
    float e0 = expf(x0 - mx), e1 = expf(x1 - mx);
    red[t] = e0 + e1;
    __syncthreads();
    for (int s = 128; s > 0; s >>= 1) {
        if (t < s) red[t] += red[t + s];
        __syncthreads();
    }
    float inv = 1.0f / red[0];
    p[t]       = e0 * inv;
    p[t + 256] = e1 * inv;
}

// out[bn,i, h*64+d] = sum_j attn[b,h,i,j] * v[bn,j, h*64+d]
// 512 batches (bn,h): M=512, N=64, K=512, NN (B row stride 1024)
__global__ void k_av() {
    int z = blockIdx.z;
    int bn = z >> 3, h = z & 7, b = bn >> 5;
    const float* A = g_dots + (size_t)(b * HH + h) * NN * NN;
    const float* B = g_kv + (size_t)bn * NN * (2 * INNERD) + INNERD + h * DH;
    float* C = g_oi + (size_t)bn * NN * INNERD + h * DH;
    gemm_body<128, 64, 16, 8, 4, false>(A, NN, B, 2 * INNERD, C, INNERD,
                                        NN, nullptr, 1.f, blockIdx.x, blockIdx.y);
}

// final: out = oi @ w_o + b_o   (M=32768, N=256, K=512, NN)
__global__ void k_final(const float* __restrict__ wo, const float* __restrict__ bo,
                        float* __restrict__ out) {
    gemm_body<128, 128, 16, 8, 8, false>(g_oi, INNERD, wo, DIMC, out, DIMC,
                                         INNERD, bo, 1.f, blockIdx.x, blockIdx.y);
}

// ---------------- launch -----------------------------------------------------
extern "C" void kernel_launch(void* const* d_in, const int* in_sizes, int n_in,
                              void* d_out, int out_size) {
    const float* x    = (const float*)d_in[0];
    const void*  mask = d_in[1];
    // d_in[2] = tie_attn_dim (always 32, shapes fixed)
    const float* dw_w = (const float*)d_in[3];
    const float* dw_b = (const float*)d_in[4];
    const float* pw_w = (const float*)d_in[5];
    const float* pw_b = (const float*)d_in[6];
    const float* w_kv = (const float*)d_in[7];
    const float* w_o  = (const float*)d_in[8];
    const float* b_o  = (const float*)d_in[9];
    float* out = (float*)d_out;

    k_detect<<<1, 256>>>((const unsigned char*)mask);
    k_norm_mask<<<(BN_TOT * NN + 255) / 256, 256>>>(mask);
    k_hasrows<<<BN_TOT, 256>>>();
    k_many<<<NB, NN>>>();

    k_conv<<<BN_TOT * NN, DIMC>>>(x, dw_w, dw_b);
    k_qproj<<<dim3(INNERD / 128, (BN_TOT * NN) / 128), 256>>>(pw_w, pw_b);
    k_kvproj<<<dim3((2 * INNERD) / 128, (BN_TOT * NN) / 128), 256>>>(x, w_kv);
    k_rotary<<<(BN_TOT * NN * INNERD) / 256, 256>>>();
    k_dots<<<dim3(NN / 128, NN / 128, NB * HH), 256>>>();
    k_softmax<<<NB * HH * NN, 256>>>();
    k_av<<<dim3(1, NN / 128, BN_TOT * HH), 256>>>();
    k_final<<<dim3(DIMC / 128, (BN_TOT * NN) / 128), 256>>>(w_o, b_o, out);
}

// round 3
// speedup vs baseline: 2.6067x; 2.6067x over previous
#include <cuda_runtime.h>
#include <cuda_bf16.h>
#include <float.h>
#include <math.h>
#include <stdint.h>

// Problem constants (fixed shapes)
#define BN_TOT 64      // b*r
#define NB 2           // b
#define RR 32          // r
#define NN 512         // n
#define DIMC 256       // DIM
#define HH 8           // heads
#define DH 64          // dim_head
#define INNERD 512     // HH*DH
#define KW 15          // conv kernel

// ---------------- scratch (device globals; no allocations allowed) ----------
__device__ float g_hdw[BN_TOT * NN * DIMC];
__device__ float g_qpre[BN_TOT * NN * INNERD];
__device__ float g_kv[BN_TOT * NN * 2 * INNERD];
__device__ float g_qr[NB * HH * NN * RR * DH];     // (b,h) x (i, r*64+d) ld 2048
__device__ float g_kr[NB * HH * NN * RR * DH];
__device__ float g_dots[NB * HH * NN * NN];
__device__ float g_oi[BN_TOT * NN * INNERD];
__device__ float g_wkvT[2 * INNERD * DIMC];        // (1024, 256) K-major
__device__ float g_woT[DIMC * INNERD];             // (256, 512) K-major
__device__ float g_vT[BN_TOT * HH * DH * NN];      // (bn,h) x (d, j) ld 512
__device__ unsigned char g_mask[BN_TOT * NN];
__device__ float g_has_rows[BN_TOT];
__device__ float g_m_any[NB * NN];
__device__ float g_alpha[NB];
__device__ float g_sin[NN * 32];
__device__ float g_cos[NN * 32];
__device__ int g_mask_mode;

// ========================= helpers ===========================================
__device__ __forceinline__ uint32_t smem_u32(const void* p) {
    uint32_t a;
    asm("{ .reg .u64 t; cvta.to.shared.u64 t, %1; cvt.u32.u64 %0, t; }" : "=r"(a) : "l"(p));
    return a;
}

#define LDSM4(r, addr)                                                          \
    asm volatile("ldmatrix.sync.aligned.m8n8.x4.shared.b16 {%0,%1,%2,%3}, [%4];" \
                 : "=r"((r)[0]), "=r"((r)[1]), "=r"((r)[2]), "=r"((r)[3])       \
                 : "r"(addr))

#define MMA16816(c, a, b)                                                       \
    asm volatile("mma.sync.aligned.m16n8k16.row.col.f32.bf16.bf16.f32 "         \
                 "{%0,%1,%2,%3}, {%4,%5,%6,%7}, {%8,%9}, {%0,%1,%2,%3};"        \
                 : "+f"((c)[0]), "+f"((c)[1]), "+f"((c)[2]), "+f"((c)[3])       \
                 : "r"((a)[0]), "r"((a)[1]), "r"((a)[2]), "r"((a)[3]),          \
                   "r"((b)[0]), "r"((b)[1]))

// byte offset in a 64B-per-row bf16 tile (32 k values/row), bank-swizzled
__device__ __forceinline__ uint32_t soff(int row, int kcol) {
    return (uint32_t)(row * 64 + ((kcol * 2) ^ (((row >> 1) & 3) << 4)));
}

// ========================= mask / small kernels ==============================
__global__ void k_detect(const unsigned char* m) {
    __shared__ int s_high, s_odd;
    if (threadIdx.x == 0) { s_high = 0; s_odd = 0; }
    __syncthreads();
    for (int idx = threadIdx.x; idx < BN_TOT * NN; idx += blockDim.x) {
        unsigned char v = m[idx];
        if (v > 1) s_high = 1;
        if ((idx & 3) && v) s_odd = 1;
    }
    __syncthreads();
    if (threadIdx.x == 0) g_mask_mode = s_high ? 2 : (s_odd ? 0 : 1);
}
__global__ void k_norm_mask(const void* m) {
    int idx = blockIdx.x * blockDim.x + threadIdx.x;
    if (idx >= BN_TOT * NN) return;
    int mode = g_mask_mode;
    unsigned char v;
    if (mode == 0)      v = (((const unsigned char*)m)[idx] != 0);
    else if (mode == 1) v = (((const int*)m)[idx] != 0);
    else                v = (((const float*)m)[idx] != 0.0f);
    g_mask[idx] = v;
}
__global__ void k_hasrows() {
    int bn = blockIdx.x;
    int any = 0;
    for (int j = threadIdx.x; j < NN; j += blockDim.x) any |= g_mask[bn * NN + j];
    __shared__ int s;
    if (threadIdx.x == 0) s = 0;
    __syncthreads();
    if (any) s = 1;
    __syncthreads();
    if (threadIdx.x == 0) g_has_rows[bn] = (float)s;
}
__global__ void k_many() {
    int b = blockIdx.x;
    int i = threadIdx.x;
    int any = 0;
    for (int r = 0; r < RR; r++) any |= g_mask[(b * RR + r) * NN + i];
    g_m_any[b * NN + i] = (float)any;
    if (i == 0) {
        float s = 0.f;
        for (int r = 0; r < RR; r++) s += g_has_rows[b * RR + r];
        g_alpha[b] = (s > 0.f) ? 0.125f * rsqrtf(s) : 0.f;
    }
}
__global__ void k_trig() {
    int i = blockIdx.x;        // 512
    int j = threadIdx.x;       // 32
    float inv = exp2f(-((float)(2 * j) / 64.0f) * 13.287712379549449f); // log2(10000)
    float ang = (float)i * inv;
    g_sin[i * 32 + j] = sinf(ang);
    g_cos[i * 32 + j] = cosf(ang);
}

// ---------------- transposes -------------------------------------------------
__global__ void k_wkvT(const float* __restrict__ w) {   // (256,1024)->(1024,256)
    int i = blockIdx.x * 256 + threadIdx.x;
    int n = i >> 8, k = i & 255;
    g_wkvT[i] = w[k * 1024 + n];
}
__global__ void k_woT(const float* __restrict__ w) {    // (512,256)->(256,512)
    int i = blockIdx.x * 256 + threadIdx.x;
    int n = i >> 9, k = i & 511;
    g_woT[i] = w[k * 256 + n];
}
__global__ void k_vT() {   // v (bn, j, 512+hd) -> g_vT[(bn*512+hd)*512 + j]
    __shared__ float t[32][33];
    int bn = blockIdx.z;
    int j0 = blockIdx.x * 32, hd0 = blockIdx.y * 32;
    int lx = threadIdx.x, ly = threadIdx.y;  // 32 x 8
    for (int dy = 0; dy < 32; dy += 8) {
        int j = j0 + ly + dy, hd = hd0 + lx;
        t[ly + dy][lx] = g_kv[((size_t)bn * NN + j) * 1024 + INNERD + hd];
    }
    __syncthreads();
    for (int dy = 0; dy < 32; dy += 8) {
        int hd = hd0 + ly + dy, j = j0 + lx;
        g_vT[((size_t)bn * 512 + hd) * 512 + j] = t[lx][ly + dy];
    }
}

// ---------------- depthwise conv ---------------------------------------------
__global__ void k_conv(const float* __restrict__ x,
                       const float* __restrict__ dww,
                       const float* __restrict__ dwb) {
    int bn = blockIdx.x >> 9;
    int i  = blockIdx.x & 511;
    int c  = threadIdx.x;
    float acc = dwb[c];
    const float* xr = x + (size_t)bn * NN * DIMC + c;
#pragma unroll
    for (int k = 0; k < KW; k++) {
        int ii = i + k - KW / 2;
        if (ii >= 0 && ii < NN) acc += xr[(size_t)ii * DIMC] * dww[c * KW + k];
    }
    g_hdw[((size_t)bn * NN + i) * DIMC + c] = acc;
}

// ---------------- rotary + relayout ------------------------------------------
__global__ void k_rotary() {
    size_t t = (size_t)blockIdx.x * blockDim.x + threadIdx.x;
    int hd = t & 511;
    int i  = (int)((t >> 9) & 511);
    int bn = (int)(t >> 18);
    int d = hd & 63, h = hd >> 6;
    int j = d >> 1;
    float s = g_sin[i * 32 + j], c = g_cos[i * 32 + j];

    size_t src = ((size_t)bn * NN + i) * INNERD + hd;
    float qv = g_qpre[src];
    float qp = g_qpre[src ^ 1];
    float qo = (d & 1) ? (qv * c + qp * s) : (qv * c - qp * s);
    qo *= g_has_rows[bn];

    size_t srck = ((size_t)bn * NN + i) * (2 * INNERD) + hd;
    float kvv = g_kv[srck];
    float kp  = g_kv[srck ^ 1];
    float ko = (d & 1) ? (kvv * c + kp * s) : (kvv * c - kp * s);

    int b = bn >> 5, r = bn & 31;
    size_t dst = (((size_t)(b * HH + h) * NN + i) * (RR * DH)) + r * DH + d;
    g_qr[dst] = qo;
    g_kr[dst] = ko;
}

// ---------------- masked softmax ---------------------------------------------
__global__ void k_softmax() {
    int row = blockIdx.x;
    int b = row >> 12;
    int i = row & 511;
    float* p = g_dots + (size_t)row * NN;
    float rv = g_m_any[b * NN + i];
    int t = threadIdx.x;

    float m0 = g_m_any[b * NN + t];
    float m1 = g_m_any[b * NN + t + 256];
    float x0 = (rv != 0.f && m0 != 0.f) ? p[t]       : -FLT_MAX;
    float x1 = (rv != 0.f && m1 != 0.f) ? p[t + 256] : -FLT_MAX;

    __shared__ float red[256];
    float mx = fmaxf(x0, x1);
    red[t] = mx;
    __syncthreads();
    for (int s = 128; s > 0; s >>= 1) {
        if (t < s) red[t] = fmaxf(red[t], red[t + s]);
        __syncthreads();
    }
    mx = red[0];
    __syncthreads();
    float e0 = expf(x0 - mx), e1 = expf(x1 - mx);
    red[t] = e0 + e1;
    __syncthreads();
    for (int s = 128; s > 0; s >>= 1) {
        if (t < s) red[t] += red[t + s];
        __syncthreads();
    }
    float inv = 1.0f / red[0];
    p[t]       = e0 * inv;
    p[t + 256] = e1 * inv;
}

// ================== mma.sync bf16-split NT GEMM ==============================
// C[M,N] = alpha * A[M,K] @ B[N,K]^T (+ bias), all fp32 in global memory.
// Block tile 128 x TN, warp tile 64 x (TN/4), K chunks of 32.
struct GemmP {
    const float* A; long long lda; long long a_bs;
    const float* B; long long ldb; long long b_bs;
    float* C; long long ldc; long long c_bs;
    int K;
    const float* bias;
    const float* alpha_vec; int alpha_shift;
    int mode;   // 0 normal batch, 1 = AV addressing
};

// convert a float2 -> (hi bf16x2, lo bf16x2) with exact truncation split
__device__ __forceinline__ void split2(float2 v, uint32_t& hp, uint32_t& lp) {
    uint32_t ux = __float_as_uint(v.x), uy = __float_as_uint(v.y);
    uint32_t hx = ux & 0xFFFF0000u, hy = uy & 0xFFFF0000u;
    float lx = v.x - __uint_as_float(hx);
    float ly = v.y - __uint_as_float(hy);
    hp = (hy) | (hx >> 16);
    lp = ((uint32_t)__bfloat16_as_ushort(__float2bfloat16(ly)) << 16) |
         (uint32_t)__bfloat16_as_ushort(__float2bfloat16(lx));
}

template <int TN>
__global__ void __launch_bounds__(256) k_mma(GemmP p) {
    constexpr int NT8 = TN / 32;   // n-tiles of 8 per warp
    constexpr int NX4 = NT8 / 2;   // x4 ldmatrix loads on B per warp
    __shared__ __align__(128) uint16_t sAhi[128 * 32], sAlo[128 * 32];
    __shared__ __align__(128) uint16_t sBhi[TN * 32],  sBlo[TN * 32];

    int tid = threadIdx.x, wid = tid >> 5, lane = tid & 31;
    int bx = blockIdx.x, by = blockIdx.y, z = blockIdx.z;

    const float* A;
    const float* B = p.B + (size_t)z * p.b_bs + (size_t)bx * TN * p.ldb;
    float* C;
    if (p.mode == 0) {
        A = p.A + (size_t)z * p.a_bs;
        C = p.C + (size_t)z * p.c_bs;
    } else {                                  // AV: z = bn*8 + h
        int bn = z >> 3, h = z & 7, b = bn >> 5;
        A = p.A + (size_t)(b * HH + h) * p.a_bs;
        C = p.C + (size_t)bn * p.c_bs + h * 64;
    }
    A += (size_t)by * 128 * p.lda;

    uint32_t aHiB = smem_u32(sAhi), aLoB = smem_u32(sAlo);
    uint32_t bHiB = smem_u32(sBhi), bLoB = smem_u32(sBlo);

    int m0 = (wid & 1) * 64;
    int n0 = (wid >> 1) * (TN / 4);

    // per-lane ldmatrix address components
    int arow = m0 + (lane & 7) + ((lane >> 3) & 1) * 8;
    int akb  = ((lane >> 4) & 1) * 8;
    int brow = n0 + (lane & 7) + ((lane >> 4) & 1) * 8;
    int bkb  = ((lane >> 3) & 1) * 8;

    float acc[4][NT8][4];
#pragma unroll
    for (int i = 0; i < 4; i++)
#pragma unroll
        for (int j = 0; j < NT8; j++)
#pragma unroll
            for (int q = 0; q < 4; q++) acc[i][j][q] = 0.f;

    int KC = p.K >> 5;
    for (int ch = 0; ch < KC; ch++) {
        int k0 = ch << 5;
        // A tile: 128 rows x 32 k  (2048 float2)
#pragma unroll 4
        for (int idx = tid; idx < 2048; idx += 256) {
            int row = idx >> 4, kp = idx & 15;
            float2 v = *(const float2*)(A + (size_t)row * p.lda + k0 + kp * 2);
            uint32_t hp, lp;
            split2(v, hp, lp);
            uint32_t off = (uint32_t)(row * 64 + ((kp * 4) ^ (((row >> 1) & 3) << 4)));
            *(uint32_t*)((char*)sAhi + off) = hp;
            *(uint32_t*)((char*)sAlo + off) = lp;
        }
        // B tile: TN rows x 32 k
#pragma unroll 4
        for (int idx = tid; idx < TN * 16; idx += 256) {
            int row = idx >> 4, kp = idx & 15;
            float2 v = *(const float2*)(B + (size_t)row * p.ldb + k0 + kp * 2);
            uint32_t hp, lp;
            split2(v, hp, lp);
            uint32_t off = (uint32_t)(row * 64 + ((kp * 4) ^ (((row >> 1) & 3) << 4)));
            *(uint32_t*)((char*)sBhi + off) = hp;
            *(uint32_t*)((char*)sBlo + off) = lp;
        }
        __syncthreads();

#pragma unroll
        for (int kk = 0; kk < 32; kk += 16) {
            uint32_t ah[4][4];
#pragma unroll
            for (int mt = 0; mt < 4; mt++)
                LDSM4(ah[mt], aHiB + soff(arow + mt * 16, kk + akb));
            uint32_t bh[NX4][4];
#pragma unroll
            for (int nx = 0; nx < NX4; nx++)
                LDSM4(bh[nx], bHiB + soff(brow + nx * 16, kk + bkb));
#pragma unroll
            for (int mt = 0; mt < 4; mt++)
#pragma unroll
                for (int nt = 0; nt < NT8; nt++)
                    MMA16816(acc[mt][nt], ah[mt], &bh[nt >> 1][(nt & 1) * 2]);

            uint32_t bl[NX4][4];
#pragma unroll
            for (int nx = 0; nx < NX4; nx++)
                LDSM4(bl[nx], bLoB + soff(brow + nx * 16, kk + bkb));
#pragma unroll
            for (int mt = 0; mt < 4; mt++)
#pragma unroll
                for (int nt = 0; nt < NT8; nt++)
                    MMA16816(acc[mt][nt], ah[mt], &bl[nt >> 1][(nt & 1) * 2]);

            uint32_t al[4][4];
#pragma unroll
            for (int mt = 0; mt < 4; mt++)
                LDSM4(al[mt], aLoB + soff(arow + mt * 16, kk + akb));
#pragma unroll
            for (int mt = 0; mt < 4; mt++)
#pragma unroll
                for (int nt = 0; nt < NT8; nt++)
                    MMA16816(acc[mt][nt], al[mt], &bh[nt >> 1][(nt & 1) * 2]);
        }
        __syncthreads();
    }

    // epilogue
    float alpha = p.alpha_vec ? p.alpha_vec[z >> p.alpha_shift] : 1.0f;
    int r0 = by * 128 + m0 + (lane >> 2);
    int c0 = bx * TN + n0 + (lane & 3) * 2;
#pragma unroll
    for (int mt = 0; mt < 4; mt++) {
#pragma unroll
        for (int nt = 0; nt < NT8; nt++) {
            int row = r0 + mt * 16;
            int col = c0 + nt * 8;
            float b0 = 0.f, b1 = 0.f;
            if (p.bias) { b0 = p.bias[col]; b1 = p.bias[col + 1]; }
            float2 v0, v1;
            v0.x = acc[mt][nt][0] * alpha + b0;
            v0.y = acc[mt][nt][1] * alpha + b1;
            v1.x = acc[mt][nt][2] * alpha + b0;
            v1.y = acc[mt][nt][3] * alpha + b1;
            *(float2*)(C + (size_t)row * p.ldc + col) = v0;
            *(float2*)(C + (size_t)(row + 8) * p.ldc + col) = v1;
        }
    }
}

// ---------------- launch -----------------------------------------------------
extern "C" void kernel_launch(void* const* d_in, const int* in_sizes, int n_in,
                              void* d_out, int out_size) {
    const float* x    = (const float*)d_in[0];
    const void*  mask = d_in[1];
    const float* dw_w = (const float*)d_in[3];
    const float* dw_b = (const float*)d_in[4];
    const float* pw_w = (const float*)d_in[5];
    const float* pw_b = (const float*)d_in[6];
    const float* w_kv = (const float*)d_in[7];
    const float* w_o  = (const float*)d_in[8];
    const float* b_o  = (const float*)d_in[9];
    float* out = (float*)d_out;

    float* g_hdw_p;   cudaGetSymbolAddress((void**)&g_hdw_p, g_hdw);
    float* g_qpre_p;  cudaGetSymbolAddress((void**)&g_qpre_p, g_qpre);
    float* g_kv_p;    cudaGetSymbolAddress((void**)&g_kv_p, g_kv);
    float* g_qr_p;    cudaGetSymbolAddress((void**)&g_qr_p, g_qr);
    float* g_kr_p;    cudaGetSymbolAddress((void**)&g_kr_p, g_kr);
    float* g_dots_p;  cudaGetSymbolAddress((void**)&g_dots_p, g_dots);
    float* g_oi_p;    cudaGetSymbolAddress((void**)&g_oi_p, g_oi);
    float* g_wkvT_p;  cudaGetSymbolAddress((void**)&g_wkvT_p, g_wkvT);
    float* g_woT_p;   cudaGetSymbolAddress((void**)&g_woT_p, g_woT);
    float* g_vT_p;    cudaGetSymbolAddress((void**)&g_vT_p, g_vT);
    float* g_alpha_p; cudaGetSymbolAddress((void**)&g_alpha_p, g_alpha);

    k_detect<<<1, 256>>>((const unsigned char*)mask);
    k_norm_mask<<<(BN_TOT * NN + 255) / 256, 256>>>(mask);
    k_hasrows<<<BN_TOT, 256>>>();
    k_many<<<NB, NN>>>();
    k_trig<<<NN, 32>>>();
    k_wkvT<<<(2 * INNERD * DIMC) / 256, 256>>>(w_kv);
    k_woT<<<(DIMC * INNERD) / 256, 256>>>(w_o);

    k_conv<<<BN_TOT * NN, DIMC>>>(x, dw_w, dw_b);

    // qproj: M=32768, N=512, K=256; B = pw_w (already N x K)
    {
        GemmP p = {g_hdw_p, DIMC, 0, pw_w, DIMC, 0, g_qpre_p, INNERD, 0,
                   DIMC, pw_b, nullptr, 0, 0};
        k_mma<128><<<dim3(4, 256, 1), 256>>>(p);
    }
    // kv: M=32768, N=1024, K=256; B = g_wkvT
    {
        GemmP p = {x, DIMC, 0, g_wkvT_p, DIMC, 0, g_kv_p, 1024, 0,
                   DIMC, nullptr, nullptr, 0, 0};
        k_mma<128><<<dim3(8, 256, 1), 256>>>(p);
    }
    k_vT<<<dim3(16, 16, BN_TOT), dim3(32, 8)>>>();
    k_rotary<<<(BN_TOT * NN * INNERD) / 256, 256>>>();
    // dots: 16 batches, M=N=512, K=2048; alpha per b = z>>3
    {
        GemmP p = {g_qr_p, 2048, (long long)NN * 2048, g_kr_p, 2048, (long long)NN * 2048,
                   g_dots_p, NN, (long long)NN * NN,
                   2048, nullptr, g_alpha_p, 3, 0};
        k_mma<128><<<dim3(4, 4, 16), 256>>>(p);
    }
    k_softmax<<<NB * HH * NN, 256>>>();
    // AV: 512 batches (bn,h), M=512, N=64, K=512; mode 1 addressing
    {
        GemmP p = {g_dots_p, NN, (long long)NN * NN, g_vT_p, NN, (long long)DH * NN,
                   g_oi_p, INNERD, (long long)NN * INNERD,
                   NN, nullptr, nullptr, 0, 1};
        k_mma<64><<<dim3(1, 4, BN_TOT * HH), 256>>>(p);
    }
    // final: M=32768, N=256, K=512; B = g_woT
    {
        GemmP p = {g_oi_p, INNERD, 0, g_woT_p, INNERD, 0, out, DIMC, 0,
                   INNERD, b_o, nullptr, 0, 0};
        k_mma<128><<<dim3(2, 256, 1), 256>>>(p);
    }
}

// round 4
// speedup vs baseline: 4.1106x; 1.5769x over previous
#include <cuda_runtime.h>
#include <cuda_bf16.h>
#include <float.h>
#include <math.h>
#include <stdint.h>

// Problem constants (fixed shapes)
#define BN_TOT 64      // b*r
#define NB 2           // b
#define RR 32          // r
#define NN 512         // n
#define DIMC 256       // DIM
#define HH 8           // heads
#define DH 64          // dim_head
#define INNERD 512     // HH*DH
#define KW 15          // conv kernel

// ---------------- scratch (device globals; no allocations allowed) ----------
__device__ float g_qpre[BN_TOT * NN * INNERD];      // q before rotary (fp32)
__device__ float g_kv[BN_TOT * NN * 2 * INNERD];    // k|v fp32
__device__ float g_dots[NB * HH * NN * NN];         // logits fp32

__device__ uint16_t g_xs_h[BN_TOT * NN * DIMC],  g_xs_l[BN_TOT * NN * DIMC];
__device__ uint16_t g_hdw_h[BN_TOT * NN * DIMC], g_hdw_l[BN_TOT * NN * DIMC];
__device__ uint16_t g_pww_h[INNERD * DIMC],      g_pww_l[INNERD * DIMC];
__device__ uint16_t g_wkvT_h[2 * INNERD * DIMC], g_wkvT_l[2 * INNERD * DIMC];
__device__ uint16_t g_woT_h[DIMC * INNERD],      g_woT_l[DIMC * INNERD];
__device__ uint16_t g_qr_h[NB * HH * NN * RR * DH], g_qr_l[NB * HH * NN * RR * DH];
__device__ uint16_t g_kr_h[NB * HH * NN * RR * DH], g_kr_l[NB * HH * NN * RR * DH];
__device__ uint16_t g_attn_h[NB * HH * NN * NN], g_attn_l[NB * HH * NN * NN];
__device__ uint16_t g_vT_h[BN_TOT * INNERD * NN], g_vT_l[BN_TOT * INNERD * NN];
__device__ uint16_t g_oi_h[BN_TOT * NN * INNERD], g_oi_l[BN_TOT * NN * INNERD];

__device__ unsigned char g_mask[BN_TOT * NN];
__device__ float g_has_rows[BN_TOT];
__device__ float g_m_any[NB * NN];
__device__ float g_alpha[NB];
__device__ float g_sin[NN * 32];
__device__ float g_cos[NN * 32];
__device__ int g_mask_mode;

// ========================= helpers ===========================================
__device__ __forceinline__ uint32_t smem_u32(const void* p) {
    uint32_t a;
    asm("{ .reg .u64 t; cvta.to.shared.u64 t, %1; cvt.u32.u64 %0, t; }" : "=r"(a) : "l"(p));
    return a;
}

#define LDSM4(r, addr)                                                          \
    asm volatile("ldmatrix.sync.aligned.m8n8.x4.shared.b16 {%0,%1,%2,%3}, [%4];" \
                 : "=r"((r)[0]), "=r"((r)[1]), "=r"((r)[2]), "=r"((r)[3])       \
                 : "r"(addr))

#define MMA16816(c, a, b)                                                       \
    asm volatile("mma.sync.aligned.m16n8k16.row.col.f32.bf16.bf16.f32 "         \
                 "{%0,%1,%2,%3}, {%4,%5,%6,%7}, {%8,%9}, {%0,%1,%2,%3};"        \
                 : "+f"((c)[0]), "+f"((c)[1]), "+f"((c)[2]), "+f"((c)[3])       \
                 : "r"((a)[0]), "r"((a)[1]), "r"((a)[2]), "r"((a)[3]),          \
                   "r"((b)[0]), "r"((b)[1]))

#define CP16(dst, src)                                                          \
    asm volatile("cp.async.cg.shared.global [%0], [%1], 16;" :: "r"(dst), "l"(src) : "memory")
#define CP_COMMIT() asm volatile("cp.async.commit_group;" ::: "memory")
#define CP_WAIT1()  asm volatile("cp.async.wait_group 1;" ::: "memory")
#define CP_WAIT0()  asm volatile("cp.async.wait_group 0;" ::: "memory")

// byte offset in a 64B-per-row bf16 tile (32 k values/row), bank-swizzled
__device__ __forceinline__ uint32_t soff(int row, int kcol) {
    return (uint32_t)(row * 64 + ((kcol * 2) ^ (((row >> 1) & 3) << 4)));
}

// exact truncation split: v = hi(bf16) + lo(bf16 rounded)
__device__ __forceinline__ void fsplit(float v, uint16_t& h, uint16_t& l) {
    uint32_t u = __float_as_uint(v);
    uint32_t hu = u & 0xFFFF0000u;
    h = (uint16_t)(hu >> 16);
    l = __bfloat16_as_ushort(__float2bfloat16(v - __uint_as_float(hu)));
}

// ========================= mask / small kernels ==============================
__global__ void k_detect(const unsigned char* m) {
    __shared__ int s_high, s_odd;
    if (threadIdx.x == 0) { s_high = 0; s_odd = 0; }
    __syncthreads();
    for (int idx = threadIdx.x; idx < BN_TOT * NN; idx += blockDim.x) {
        unsigned char v = m[idx];
        if (v > 1) s_high = 1;
        if ((idx & 3) && v) s_odd = 1;
    }
    __syncthreads();
    if (threadIdx.x == 0) g_mask_mode = s_high ? 2 : (s_odd ? 0 : 1);
}
__global__ void k_norm_mask(const void* m) {
    int idx = blockIdx.x * blockDim.x + threadIdx.x;
    if (idx >= BN_TOT * NN) return;
    int mode = g_mask_mode;
    unsigned char v;
    if (mode == 0)      v = (((const unsigned char*)m)[idx] != 0);
    else if (mode == 1) v = (((const int*)m)[idx] != 0);
    else                v = (((const float*)m)[idx] != 0.0f);
    g_mask[idx] = v;
}
__global__ void k_hasrows() {
    int bn = blockIdx.x;
    int any = 0;
    for (int j = threadIdx.x; j < NN; j += blockDim.x) any |= g_mask[bn * NN + j];
    __shared__ int s;
    if (threadIdx.x == 0) s = 0;
    __syncthreads();
    if (any) s = 1;
    __syncthreads();
    if (threadIdx.x == 0) g_has_rows[bn] = (float)s;
}
__global__ void k_many() {
    int b = blockIdx.x;
    int i = threadIdx.x;
    int any = 0;
    for (int r = 0; r < RR; r++) any |= g_mask[(b * RR + r) * NN + i];
    g_m_any[b * NN + i] = (float)any;
    if (i == 0) {
        float s = 0.f;
        for (int r = 0; r < RR; r++) s += g_has_rows[b * RR + r];
        g_alpha[b] = (s > 0.f) ? 0.125f * rsqrtf(s) : 0.f;
    }
}
__global__ void k_trig() {
    int i = blockIdx.x;        // 512
    int j = threadIdx.x;       // 32
    float inv = exp2f(-((float)(2 * j) / 64.0f) * 13.287712379549449f);
    float ang = (float)i * inv;
    g_sin[i * 32 + j] = sinf(ang);
    g_cos[i * 32 + j] = cosf(ang);
}

// ---------------- splits / transposes ---------------------------------------
__global__ void k_split(const float* __restrict__ src, uint16_t* __restrict__ h,
                        uint16_t* __restrict__ l, int n) {
    int i = blockIdx.x * blockDim.x + threadIdx.x;
    if (i >= n) return;
    fsplit(src[i], h[i], l[i]);
}
__global__ void k_wkvT(const float* __restrict__ w) {   // (256,1024)->(1024,256) split
    int i = blockIdx.x * 256 + threadIdx.x;
    int n = i >> 8, k = i & 255;
    fsplit(w[k * 1024 + n], g_wkvT_h[i], g_wkvT_l[i]);
}
__global__ void k_woT(const float* __restrict__ w) {    // (512,256)->(256,512) split
    int i = blockIdx.x * 256 + threadIdx.x;
    int n = i >> 9, k = i & 511;
    fsplit(w[k * 256 + n], g_woT_h[i], g_woT_l[i]);
}
__global__ void k_vT() {   // v (bn, j, 512+hd) -> vT[(bn*512+hd)*512 + j] split
    __shared__ float t[32][33];
    int bn = blockIdx.z;
    int j0 = blockIdx.x * 32, hd0 = blockIdx.y * 32;
    int lx = threadIdx.x, ly = threadIdx.y;  // 32 x 8
    for (int dy = 0; dy < 32; dy += 8) {
        int j = j0 + ly + dy, hd = hd0 + lx;
        t[ly + dy][lx] = g_kv[((size_t)bn * NN + j) * 1024 + INNERD + hd];
    }
    __syncthreads();
    for (int dy = 0; dy < 32; dy += 8) {
        int hd = hd0 + ly + dy, j = j0 + lx;
        size_t o = ((size_t)bn * 512 + hd) * 512 + j;
        fsplit(t[lx][ly + dy], g_vT_h[o], g_vT_l[o]);
    }
}

// ---------------- depthwise conv (writes split) ------------------------------
__global__ void k_conv(const float* __restrict__ x,
                       const float* __restrict__ dww,
                       const float* __restrict__ dwb) {
    int bn = blockIdx.x >> 9;
    int i  = blockIdx.x & 511;
    int c  = threadIdx.x;
    float acc = dwb[c];
    const float* xr = x + (size_t)bn * NN * DIMC + c;
#pragma unroll
    for (int k = 0; k < KW; k++) {
        int ii = i + k - KW / 2;
        if (ii >= 0 && ii < NN) acc += xr[(size_t)ii * DIMC] * dww[c * KW + k];
    }
    size_t o = ((size_t)bn * NN + i) * DIMC + c;
    fsplit(acc, g_hdw_h[o], g_hdw_l[o]);
}

// ---------------- rotary + relayout (writes split) ---------------------------
__global__ void k_rotary() {
    size_t t = (size_t)blockIdx.x * blockDim.x + threadIdx.x;
    int hd = t & 511;
    int i  = (int)((t >> 9) & 511);
    int bn = (int)(t >> 18);
    int d = hd & 63, h = hd >> 6;
    int j = d >> 1;
    float s = g_sin[i * 32 + j], c = g_cos[i * 32 + j];

    size_t src = ((size_t)bn * NN + i) * INNERD + hd;
    float qv = g_qpre[src];
    float qp = g_qpre[src ^ 1];
    float qo = (d & 1) ? (qv * c + qp * s) : (qv * c - qp * s);
    qo *= g_has_rows[bn];

    size_t srck = ((size_t)bn * NN + i) * (2 * INNERD) + hd;
    float kvv = g_kv[srck];
    float kp  = g_kv[srck ^ 1];
    float ko = (d & 1) ? (kvv * c + kp * s) : (kvv * c - kp * s);

    int b = bn >> 5, r = bn & 31;
    size_t dst = (((size_t)(b * HH + h) * NN + i) * (RR * DH)) + r * DH + d;
    fsplit(qo, g_qr_h[dst], g_qr_l[dst]);
    fsplit(ko, g_kr_h[dst], g_kr_l[dst]);
}

// ---------------- masked softmax (writes split) ------------------------------
__global__ void k_softmax() {
    int row = blockIdx.x;
    int b = row >> 12;
    int i = row & 511;
    const float* p = g_dots + (size_t)row * NN;
    float rv = g_m_any[b * NN + i];
    int t = threadIdx.x;

    float m0 = g_m_any[b * NN + t];
    float m1 = g_m_any[b * NN + t + 256];
    float x0 = (rv != 0.f && m0 != 0.f) ? p[t]       : -FLT_MAX;
    float x1 = (rv != 0.f && m1 != 0.f) ? p[t + 256] : -FLT_MAX;

    __shared__ float red[256];
    float mx = fmaxf(x0, x1);
    red[t] = mx;
    __syncthreads();
    for (int s = 128; s > 0; s >>= 1) {
        if (t < s) red[t] = fmaxf(red[t], red[t + s]);
        __syncthreads();
    }
    mx = red[0];
    __syncthreads();
    float e0 = expf(x0 - mx), e1 = expf(x1 - mx);
    red[t] = e0 + e1;
    __syncthreads();
    for (int s = 128; s > 0; s >>= 1) {
        if (t < s) red[t] += red[t + s];
        __syncthreads();
    }
    float inv = 1.0f / red[0];
    size_t o = (size_t)row * NN;
    fsplit(e0 * inv, g_attn_h[o + t],       g_attn_l[o + t]);
    fsplit(e1 * inv, g_attn_h[o + t + 256], g_attn_l[o + t + 256]);
}

// ================== mma.sync bf16-split NT GEMM (cp.async pipelined) =========
// C[M,N] = alpha * A[M,K] @ B[N,K]^T (+ bias). Operands pre-split bf16 hi/lo.
// Block tile 128 x TN, warp tile 64 x (TN/4), K chunks of 32, 2-stage pipeline.
struct GemmP {
    const uint16_t *Ah, *Al; long long lda; long long a_bs;
    const uint16_t *Bh, *Bl; long long ldb; long long b_bs;
    float* C;                                  // fp32 out (or null)
    uint16_t *Ch, *Cl;                         // split out (or null)
    long long ldc; long long c_bs;
    int K;
    const float* bias;
    const float* alpha_vec; int alpha_shift;
    int mode;   // 0 normal batch, 1 = AV addressing
};

template <int TN>
__global__ void __launch_bounds__(256) k_mma(GemmP p) {
    constexpr int NT8 = TN / 32;   // n-tiles of 8 per warp
    constexpr int NX4 = NT8 / 2;   // x4 ldmatrix loads on B per warp
    constexpr uint32_t SS = 16384 + TN * 128;    // stage stride bytes
    extern __shared__ __align__(128) char dsm[];
    uint32_t sb = smem_u32(dsm);

    int tid = threadIdx.x, wid = tid >> 5, lane = tid & 31;
    int bx = blockIdx.x, by = blockIdx.y, z = blockIdx.z;

    size_t abase, cbase;
    size_t bbase = (size_t)z * p.b_bs + (size_t)bx * TN * p.ldb;
    if (p.mode == 0) {
        abase = (size_t)z * p.a_bs;
        cbase = (size_t)z * p.c_bs;
    } else {                                  // AV: z = bn*8 + h
        int bn = z >> 3, h = z & 7, b = bn >> 5;
        abase = (size_t)(b * HH + h) * p.a_bs;
        cbase = (size_t)bn * p.c_bs + h * 64;
    }
    abase += (size_t)by * 128 * p.lda;
    const uint16_t* Ah = p.Ah + abase;
    const uint16_t* Al = p.Al + abase;
    const uint16_t* Bh = p.Bh + bbase;
    const uint16_t* Bl = p.Bl + bbase;

    int m0 = (wid & 1) * 64;
    int n0 = (wid >> 1) * (TN / 4);
    int arow = m0 + (lane & 7) + ((lane >> 3) & 1) * 8;
    int akb  = ((lane >> 4) & 1) * 8;
    int brow = n0 + (lane & 7) + ((lane >> 4) & 1) * 8;
    int bkb  = ((lane >> 3) & 1) * 8;

    float acc[4][NT8][4];
#pragma unroll
    for (int i = 0; i < 4; i++)
#pragma unroll
        for (int j = 0; j < NT8; j++)
#pragma unroll
            for (int q = 0; q < 4; q++) acc[i][j][q] = 0.f;

    int KC = p.K >> 5;

    // stage loader
    auto load_stage = [&](int st, int k0) {
        uint32_t base = sb + (uint32_t)st * SS;
#pragma unroll 2
        for (int idx = tid; idx < 512; idx += 256) {
            int row = idx >> 2, c = idx & 3;
            uint32_t off = (uint32_t)(row * 64 + ((c * 16) ^ (((row >> 1) & 3) << 4)));
            const uint16_t* sh = Ah + (size_t)row * p.lda + k0 + c * 8;
            const uint16_t* sl = Al + (size_t)row * p.lda + k0 + c * 8;
            CP16(base + off, sh);
            CP16(base + 8192 + off, sl);
        }
#pragma unroll 2
        for (int idx = tid; idx < TN * 4; idx += 256) {
            int row = idx >> 2, c = idx & 3;
            uint32_t off = (uint32_t)(row * 64 + ((c * 16) ^ (((row >> 1) & 3) << 4)));
            const uint16_t* sh = Bh + (size_t)row * p.ldb + k0 + c * 8;
            const uint16_t* sl = Bl + (size_t)row * p.ldb + k0 + c * 8;
            CP16(base + 16384 + off, sh);
            CP16(base + 16384 + TN * 64 + off, sl);
        }
    };

    load_stage(0, 0);
    CP_COMMIT();

    for (int ch = 0; ch < KC; ch++) {
        if (ch + 1 < KC) {
            load_stage((ch + 1) & 1, (ch + 1) << 5);
            CP_COMMIT();
            CP_WAIT1();
        } else {
            CP_WAIT0();
        }
        __syncthreads();

        uint32_t base = sb + (uint32_t)(ch & 1) * SS;
        uint32_t aHiB = base, aLoB = base + 8192;
        uint32_t bHiB = base + 16384, bLoB = base + 16384 + TN * 64;

#pragma unroll
        for (int kk = 0; kk < 32; kk += 16) {
            uint32_t ah[4][4];
#pragma unroll
            for (int mt = 0; mt < 4; mt++)
                LDSM4(ah[mt], aHiB + soff(arow + mt * 16, kk + akb));
            uint32_t bh[NX4][4];
#pragma unroll
            for (int nx = 0; nx < NX4; nx++)
                LDSM4(bh[nx], bHiB + soff(brow + nx * 16, kk + bkb));
#pragma unroll
            for (int mt = 0; mt < 4; mt++)
#pragma unroll
                for (int nt = 0; nt < NT8; nt++)
                    MMA16816(acc[mt][nt], ah[mt], &bh[nt >> 1][(nt & 1) * 2]);

            uint32_t bl[NX4][4];
#pragma unroll
            for (int nx = 0; nx < NX4; nx++)
                LDSM4(bl[nx], bLoB + soff(brow + nx * 16, kk + bkb));
#pragma unroll
            for (int mt = 0; mt < 4; mt++)
#pragma unroll
                for (int nt = 0; nt < NT8; nt++)
                    MMA16816(acc[mt][nt], ah[mt], &bl[nt >> 1][(nt & 1) * 2]);

            uint32_t al[4][4];
#pragma unroll
            for (int mt = 0; mt < 4; mt++)
                LDSM4(al[mt], aLoB + soff(arow + mt * 16, kk + akb));
#pragma unroll
            for (int mt = 0; mt < 4; mt++)
#pragma unroll
                for (int nt = 0; nt < NT8; nt++)
                    MMA16816(acc[mt][nt], al[mt], &bh[nt >> 1][(nt & 1) * 2]);
        }
        __syncthreads();
    }

    // epilogue
    float alpha = p.alpha_vec ? p.alpha_vec[z >> p.alpha_shift] : 1.0f;
    int r0 = by * 128 + m0 + (lane >> 2);
    int c0 = bx * TN + n0 + (lane & 3) * 2;
#pragma unroll
    for (int mt = 0; mt < 4; mt++) {
#pragma unroll
        for (int nt = 0; nt < NT8; nt++) {
            int row = r0 + mt * 16;
            int col = c0 + nt * 8;
            float b0 = 0.f, b1 = 0.f;
            if (p.bias) { b0 = p.bias[col]; b1 = p.bias[col + 1]; }
            float v00 = acc[mt][nt][0] * alpha + b0;
            float v01 = acc[mt][nt][1] * alpha + b1;
            float v10 = acc[mt][nt][2] * alpha + b0;
            float v11 = acc[mt][nt][3] * alpha + b1;
            if (p.C) {
                *(float2*)(p.C + cbase + (size_t)row * p.ldc + col) = make_float2(v00, v01);
                *(float2*)(p.C + cbase + (size_t)(row + 8) * p.ldc + col) = make_float2(v10, v11);
            }
            if (p.Ch) {
                uint16_t h0, l0, h1, l1;
                fsplit(v00, h0, l0); fsplit(v01, h1, l1);
                *(uint32_t*)(p.Ch + cbase + (size_t)row * p.ldc + col) = (uint32_t)h0 | ((uint32_t)h1 << 16);
                *(uint32_t*)(p.Cl + cbase + (size_t)row * p.ldc + col) = (uint32_t)l0 | ((uint32_t)l1 << 16);
                fsplit(v10, h0, l0); fsplit(v11, h1, l1);
                *(uint32_t*)(p.Ch + cbase + (size_t)(row + 8) * p.ldc + col) = (uint32_t)h0 | ((uint32_t)h1 << 16);
                *(uint32_t*)(p.Cl + cbase + (size_t)(row + 8) * p.ldc + col) = (uint32_t)l0 | ((uint32_t)l1 << 16);
            }
        }
    }
}

// ---------------- launch -----------------------------------------------------
#define SYM(var, sym) decltype(&sym[0]) var; cudaGetSymbolAddress((void**)&var, sym)

extern "C" void kernel_launch(void* const* d_in, const int* in_sizes, int n_in,
                              void* d_out, int out_size) {
    const float* x    = (const float*)d_in[0];
    const void*  mask = d_in[1];
    const float* dw_w = (const float*)d_in[3];
    const float* dw_b = (const float*)d_in[4];
    const float* pw_w = (const float*)d_in[5];
    const float* pw_b = (const float*)d_in[6];
    const float* w_kv = (const float*)d_in[7];
    const float* w_o  = (const float*)d_in[8];
    const float* b_o  = (const float*)d_in[9];
    float* out = (float*)d_out;

    const int SM128 = 2 * (16384 + 128 * 128);   // 65536
    const int SM64  = 2 * (16384 + 64 * 128);    // 49152
    cudaFuncSetAttribute(k_mma<128>, cudaFuncAttributeMaxDynamicSharedMemorySize, SM128);
    cudaFuncSetAttribute(k_mma<64>,  cudaFuncAttributeMaxDynamicSharedMemorySize, SM64);

    SYM(qpre_p, g_qpre);  SYM(kv_p, g_kv);  SYM(dots_p, g_dots);
    SYM(xs_h, g_xs_h);    SYM(xs_l, g_xs_l);
    SYM(hdw_h, g_hdw_h);  SYM(hdw_l, g_hdw_l);
    SYM(pww_h, g_pww_h);  SYM(pww_l, g_pww_l);
    SYM(wkvT_h, g_wkvT_h); SYM(wkvT_l, g_wkvT_l);
    SYM(woT_h, g_woT_h);  SYM(woT_l, g_woT_l);
    SYM(qr_h, g_qr_h);    SYM(qr_l, g_qr_l);
    SYM(kr_h, g_kr_h);    SYM(kr_l, g_kr_l);
    SYM(attn_h, g_attn_h); SYM(attn_l, g_attn_l);
    SYM(vT_h, g_vT_h);    SYM(vT_l, g_vT_l);
    SYM(oi_h, g_oi_h);    SYM(oi_l, g_oi_l);
    SYM(alpha_p, g_alpha);

    k_detect<<<1, 256>>>((const unsigned char*)mask);
    k_norm_mask<<<(BN_TOT * NN + 255) / 256, 256>>>(mask);
    k_hasrows<<<BN_TOT, 256>>>();
    k_many<<<NB, NN>>>();
    k_trig<<<NN, 32>>>();

    k_split<<<(BN_TOT * NN * DIMC) / 256, 256>>>(x, xs_h, xs_l, BN_TOT * NN * DIMC);
    k_split<<<(INNERD * DIMC) / 256, 256>>>(pw_w, pww_h, pww_l, INNERD * DIMC);
    k_wkvT<<<(2 * INNERD * DIMC) / 256, 256>>>(w_kv);
    k_woT<<<(DIMC * INNERD) / 256, 256>>>(w_o);

    k_conv<<<BN_TOT * NN, DIMC>>>(x, dw_w, dw_b);

    // qproj: M=32768, N=512, K=256 -> g_qpre fp32 (+bias)
    {
        GemmP p = {hdw_h, hdw_l, DIMC, 0, pww_h, pww_l, DIMC, 0,
                   qpre_p, nullptr, nullptr, INNERD, 0,
                   DIMC, pw_b, nullptr, 0, 0};
        k_mma<128><<<dim3(4, 256, 1), 256, SM128>>>(p);
    }
    // kv: M=32768, N=1024, K=256 -> g_kv fp32
    {
        GemmP p = {xs_h, xs_l, DIMC, 0, wkvT_h, wkvT_l, DIMC, 0,
                   kv_p, nullptr, nullptr, 1024, 0,
                   DIMC, nullptr, nullptr, 0, 0};
        k_mma<128><<<dim3(8, 256, 1), 256, SM128>>>(p);
    }
    k_vT<<<dim3(16, 16, BN_TOT), dim3(32, 8)>>>();
    k_rotary<<<(BN_TOT * NN * INNERD) / 256, 256>>>();
    // dots: 16 batches, M=N=512, K=2048 -> g_dots fp32 (alpha per b)
    {
        GemmP p = {qr_h, qr_l, 2048, (long long)NN * 2048, kr_h, kr_l, 2048, (long long)NN * 2048,
                   dots_p, nullptr, nullptr, NN, (long long)NN * NN,
                   2048, nullptr, alpha_p, 3, 0};
        k_mma<128><<<dim3(4, 4, 16), 256, SM128>>>(p);
    }
    k_softmax<<<NB * HH * NN, 256>>>();
    // AV: 512 batches (bn,h), M=512, N=64, K=512 -> oi split
    {
        GemmP p = {attn_h, attn_l, NN, (long long)NN * NN, vT_h, vT_l, NN, (long long)DH * NN,
                   nullptr, oi_h, oi_l, INNERD, (long long)NN * INNERD,
                   NN, nullptr, nullptr, 0, 1};
        k_mma<64><<<dim3(1, 4, BN_TOT * HH), 256, SM64>>>(p);
    }
    // final: M=32768, N=256, K=512 -> out fp32 (+bias)
    {
        GemmP p = {oi_h, oi_l, INNERD, 0, woT_h, woT_l, INNERD, 0,
                   out, nullptr, nullptr, DIMC, 0,
                   INNERD, b_o, nullptr, 0, 0};
        k_mma<128><<<dim3(2, 256, 1), 256, SM128>>>(p);
    }
}

// round 5
// speedup vs baseline: 4.2780x; 1.0407x over previous
#include <cuda_runtime.h>
#include <cuda_bf16.h>
#include <float.h>
#include <math.h>
#include <stdint.h>

// Problem constants (fixed shapes)
#define BN_TOT 64      // b*r
#define NB 2           // b
#define RR 32          // r
#define NN 512         // n
#define DIMC 256       // DIM
#define HH 8           // heads
#define DH 64          // dim_head
#define INNERD 512     // HH*DH
#define KW 15          // conv kernel

// ---------------- scratch (device globals; no allocations allowed) ----------
__device__ float g_v[BN_TOT * NN * INNERD];         // v fp32 (bn, i, hd)
__device__ float g_dots[NB * HH * NN * NN];         // logits fp32

__device__ uint16_t g_xs_h[BN_TOT * NN * DIMC],  g_xs_l[BN_TOT * NN * DIMC];
__device__ uint16_t g_hdw_h[BN_TOT * NN * DIMC], g_hdw_l[BN_TOT * NN * DIMC];
__device__ uint16_t g_pww_h[INNERD * DIMC],      g_pww_l[INNERD * DIMC];
__device__ uint16_t g_wkvT_h[2 * INNERD * DIMC], g_wkvT_l[2 * INNERD * DIMC];
__device__ uint16_t g_woT_h[DIMC * INNERD],      g_woT_l[DIMC * INNERD];
__device__ uint16_t g_qr_h[NB * HH * NN * RR * DH], g_qr_l[NB * HH * NN * RR * DH];
__device__ uint16_t g_kr_h[NB * HH * NN * RR * DH], g_kr_l[NB * HH * NN * RR * DH];
__device__ uint16_t g_attn_h[NB * HH * NN * NN], g_attn_l[NB * HH * NN * NN];
__device__ uint16_t g_vT_h[BN_TOT * INNERD * NN], g_vT_l[BN_TOT * INNERD * NN];
__device__ uint16_t g_oi_h[BN_TOT * NN * INNERD], g_oi_l[BN_TOT * NN * INNERD];

__device__ unsigned char g_mask[BN_TOT * NN];
__device__ float g_has_rows[BN_TOT];
__device__ float g_m_any[NB * NN];
__device__ float g_alpha[NB];
__device__ float g_sin[NN * 32];
__device__ float g_cos[NN * 32];
__device__ int g_mask_mode;

// ========================= helpers ===========================================
__device__ __forceinline__ uint32_t smem_u32(const void* p) {
    uint32_t a;
    asm("{ .reg .u64 t; cvta.to.shared.u64 t, %1; cvt.u32.u64 %0, t; }" : "=r"(a) : "l"(p));
    return a;
}

#define LDSM4(r, addr)                                                          \
    asm volatile("ldmatrix.sync.aligned.m8n8.x4.shared.b16 {%0,%1,%2,%3}, [%4];" \
                 : "=r"((r)[0]), "=r"((r)[1]), "=r"((r)[2]), "=r"((r)[3])       \
                 : "r"(addr))

#define MMA16816(c, a, b)                                                       \
    asm volatile("mma.sync.aligned.m16n8k16.row.col.f32.bf16.bf16.f32 "         \
                 "{%0,%1,%2,%3}, {%4,%5,%6,%7}, {%8,%9}, {%0,%1,%2,%3};"        \
                 : "+f"((c)[0]), "+f"((c)[1]), "+f"((c)[2]), "+f"((c)[3])       \
                 : "r"((a)[0]), "r"((a)[1]), "r"((a)[2]), "r"((a)[3]),          \
                   "r"((b)[0]), "r"((b)[1]))

#define CP16(dst, src)                                                          \
    asm volatile("cp.async.cg.shared.global [%0], [%1], 16;" :: "r"(dst), "l"(src) : "memory")
#define CP_COMMIT() asm volatile("cp.async.commit_group;" ::: "memory")
#define CP_WAIT1()  asm volatile("cp.async.wait_group 1;" ::: "memory")
#define CP_WAIT0()  asm volatile("cp.async.wait_group 0;" ::: "memory")

// byte offset in a 64B-per-row bf16 tile (32 k values/row), bank-swizzled
__device__ __forceinline__ uint32_t soff(int row, int kcol) {
    return (uint32_t)(row * 64 + ((kcol * 2) ^ (((row >> 1) & 3) << 4)));
}

// exact truncation split: v = hi(bf16) + lo(bf16 rounded)
__device__ __forceinline__ void fsplit(float v, uint16_t& h, uint16_t& l) {
    uint32_t u = __float_as_uint(v);
    uint32_t hu = u & 0xFFFF0000u;
    h = (uint16_t)(hu >> 16);
    l = __bfloat16_as_ushort(__float2bfloat16(v - __uint_as_float(hu)));
}
__device__ __forceinline__ uint32_t pack_h(float a, float b) {
    uint16_t h0, l0, h1, l1;
    fsplit(a, h0, l0); fsplit(b, h1, l1);
    (void)l0; (void)l1;
    return (uint32_t)h0 | ((uint32_t)h1 << 16);
}

// ========================= mask / small kernels ==============================
__global__ void k_detect(const unsigned char* m) {
    __shared__ int s_high, s_odd;
    if (threadIdx.x == 0) { s_high = 0; s_odd = 0; }
    __syncthreads();
    for (int idx = threadIdx.x; idx < BN_TOT * NN; idx += blockDim.x) {
        unsigned char v = m[idx];
        if (v > 1) s_high = 1;
        if ((idx & 3) && v) s_odd = 1;
    }
    __syncthreads();
    if (threadIdx.x == 0) g_mask_mode = s_high ? 2 : (s_odd ? 0 : 1);
}
__global__ void k_norm_mask(const void* m) {
    int idx = blockIdx.x * blockDim.x + threadIdx.x;
    if (idx >= BN_TOT * NN) return;
    int mode = g_mask_mode;
    unsigned char v;
    if (mode == 0)      v = (((const unsigned char*)m)[idx] != 0);
    else if (mode == 1) v = (((const int*)m)[idx] != 0);
    else                v = (((const float*)m)[idx] != 0.0f);
    g_mask[idx] = v;
}
__global__ void k_hasrows() {
    int bn = blockIdx.x;
    int any = 0;
    for (int j = threadIdx.x; j < NN; j += blockDim.x) any |= g_mask[bn * NN + j];
    __shared__ int s;
    if (threadIdx.x == 0) s = 0;
    __syncthreads();
    if (any) s = 1;
    __syncthreads();
    if (threadIdx.x == 0) g_has_rows[bn] = (float)s;
}
__global__ void k_many() {
    int b = blockIdx.x;
    int i = threadIdx.x;
    int any = 0;
    for (int r = 0; r < RR; r++) any |= g_mask[(b * RR + r) * NN + i];
    g_m_any[b * NN + i] = (float)any;
    if (i == 0) {
        float s = 0.f;
        for (int r = 0; r < RR; r++) s += g_has_rows[b * RR + r];
        g_alpha[b] = (s > 0.f) ? 0.125f * rsqrtf(s) : 0.f;
    }
}
__global__ void k_trig() {
    int i = blockIdx.x;        // 512
    int j = threadIdx.x;       // 32
    float inv = exp2f(-((float)(2 * j) / 64.0f) * 13.287712379549449f);
    float ang = (float)i * inv;
    g_sin[i * 32 + j] = sinf(ang);
    g_cos[i * 32 + j] = cosf(ang);
}

// ---------------- splits / transposes ---------------------------------------
__global__ void k_split(const float* __restrict__ src, uint16_t* __restrict__ h,
                        uint16_t* __restrict__ l, int n) {
    int i = blockIdx.x * blockDim.x + threadIdx.x;
    if (i >= n) return;
    fsplit(src[i], h[i], l[i]);
}
__global__ void k_wkvT(const float* __restrict__ w) {   // (256,1024)->(1024,256) split
    int i = blockIdx.x * 256 + threadIdx.x;
    int n = i >> 8, k = i & 255;
    fsplit(w[k * 1024 + n], g_wkvT_h[i], g_wkvT_l[i]);
}
__global__ void k_woT(const float* __restrict__ w) {    // (512,256)->(256,512) split
    int i = blockIdx.x * 256 + threadIdx.x;
    int n = i >> 9, k = i & 511;
    fsplit(w[k * 256 + n], g_woT_h[i], g_woT_l[i]);
}
__global__ void k_vT() {   // v (bn, j, hd) -> vT[(bn*512+hd)*512 + j] split
    __shared__ float t[32][33];
    int bn = blockIdx.z;
    int j0 = blockIdx.x * 32, hd0 = blockIdx.y * 32;
    int lx = threadIdx.x, ly = threadIdx.y;  // 32 x 8
    for (int dy = 0; dy < 32; dy += 8) {
        int j = j0 + ly + dy, hd = hd0 + lx;
        t[ly + dy][lx] = g_v[((size_t)bn * NN + j) * INNERD + hd];
    }
    __syncthreads();
    for (int dy = 0; dy < 32; dy += 8) {
        int hd = hd0 + ly + dy, j = j0 + lx;
        size_t o = ((size_t)bn * 512 + hd) * 512 + j;
        fsplit(t[lx][ly + dy], g_vT_h[o], g_vT_l[o]);
    }
}

// ---------------- depthwise conv (writes split) ------------------------------
__global__ void k_conv(const float* __restrict__ x,
                       const float* __restrict__ dww,
                       const float* __restrict__ dwb) {
    int bn = blockIdx.x >> 9;
    int i  = blockIdx.x & 511;
    int c  = threadIdx.x;
    float acc = dwb[c];
    const float* xr = x + (size_t)bn * NN * DIMC + c;
#pragma unroll
    for (int k = 0; k < KW; k++) {
        int ii = i + k - KW / 2;
        if (ii >= 0 && ii < NN) acc += xr[(size_t)ii * DIMC] * dww[c * KW + k];
    }
    size_t o = ((size_t)bn * NN + i) * DIMC + c;
    fsplit(acc, g_hdw_h[o], g_hdw_l[o]);
}

// ---------------- masked softmax (writes split) ------------------------------
__global__ void k_softmax() {
    int row = blockIdx.x;
    int b = row >> 12;
    int i = row & 511;
    const float* p = g_dots + (size_t)row * NN;
    float rv = g_m_any[b * NN + i];
    int t = threadIdx.x;

    float m0 = g_m_any[b * NN + t];
    float m1 = g_m_any[b * NN + t + 256];
    float x0 = (rv != 0.f && m0 != 0.f) ? p[t]       : -FLT_MAX;
    float x1 = (rv != 0.f && m1 != 0.f) ? p[t + 256] : -FLT_MAX;

    __shared__ float red[256];
    float mx = fmaxf(x0, x1);
    red[t] = mx;
    __syncthreads();
    for (int s = 128; s > 0; s >>= 1) {
        if (t < s) red[t] = fmaxf(red[t], red[t + s]);
        __syncthreads();
    }
    mx = red[0];
    __syncthreads();
    float e0 = expf(x0 - mx), e1 = expf(x1 - mx);
    red[t] = e0 + e1;
    __syncthreads();
    for (int s = 128; s > 0; s >>= 1) {
        if (t < s) red[t] += red[t + s];
        __syncthreads();
    }
    float inv = 1.0f / red[0];
    size_t o = (size_t)row * NN;
    fsplit(e0 * inv, g_attn_h[o + t],       g_attn_l[o + t]);
    fsplit(e1 * inv, g_attn_h[o + t + 256], g_attn_l[o + t + 256]);
}

// ================== mma.sync bf16-split NT GEMM (cp.async pipelined) =========
struct GemmP {
    const uint16_t *Ah, *Al; long long lda; long long a_bs;
    const uint16_t *Bh, *Bl; long long ldb; long long b_bs;
    float* C;                                  // fp32 out (or null)
    uint16_t *Ch, *Cl;                         // split out (or null)
    long long ldc; long long c_bs;
    int K;
    const float* bias;
    const float* alpha_vec; int alpha_shift;
    int mode;   // 0 normal batch, 1 = AV addressing
    int emode;  // 0 plain, 1 rotary->qr (has_rows), 2 rotary->kr
};

// rotary epilogue: (v_e, v_o) at global row `row`, even col `col` (hd space)
__device__ __forceinline__ void rot_store(uint16_t* __restrict__ Rh,
                                          uint16_t* __restrict__ Rl,
                                          int row, int col, float ve, float vo,
                                          bool isq) {
    int i = row & 511, bn = row >> 9;
    int h = col >> 6, d = col & 63, j = d >> 1;
    float s = g_sin[i * 32 + j], c = g_cos[i * 32 + j];
    float oe = ve * c - vo * s;
    float oo = vo * c + ve * s;
    if (isq) {
        float hr = g_has_rows[bn];
        oe *= hr; oo *= hr;
    }
    int b = bn >> 5, r = bn & 31;
    size_t dst = (((size_t)(b * HH + h) * NN + i) * (RR * DH)) + r * DH + d;
    uint16_t h0, l0, h1, l1;
    fsplit(oe, h0, l0); fsplit(oo, h1, l1);
    *(uint32_t*)(Rh + dst) = (uint32_t)h0 | ((uint32_t)h1 << 16);
    *(uint32_t*)(Rl + dst) = (uint32_t)l0 | ((uint32_t)l1 << 16);
}

template <int TN>
__global__ void __launch_bounds__(256) k_mma(GemmP p) {
    constexpr int NT8 = TN / 32;
    constexpr int NX4 = NT8 / 2;
    constexpr uint32_t SS = 16384 + TN * 128;    // stage stride bytes
    extern __shared__ __align__(128) char dsm[];
    uint32_t sb = smem_u32(dsm);

    int tid = threadIdx.x, wid = tid >> 5, lane = tid & 31;
    int bx = blockIdx.x, by = blockIdx.y, z = blockIdx.z;

    size_t abase, cbase;
    size_t bbase = (size_t)z * p.b_bs + (size_t)bx * TN * p.ldb;
    if (p.mode == 0) {
        abase = (size_t)z * p.a_bs;
        cbase = (size_t)z * p.c_bs;
    } else {                                  // AV: z = bn*8 + h
        int bn = z >> 3, h = z & 7, b = bn >> 5;
        abase = (size_t)(b * HH + h) * p.a_bs;
        cbase = (size_t)bn * p.c_bs + h * 64;
    }
    abase += (size_t)by * 128 * p.lda;
    const uint16_t* Ah = p.Ah + abase;
    const uint16_t* Al = p.Al + abase;
    const uint16_t* Bh = p.Bh + bbase;
    const uint16_t* Bl = p.Bl + bbase;

    int m0 = (wid & 1) * 64;
    int n0 = (wid >> 1) * (TN / 4);
    int arow = m0 + (lane & 7) + ((lane >> 3) & 1) * 8;
    int akb  = ((lane >> 4) & 1) * 8;
    int brow = n0 + (lane & 7) + ((lane >> 4) & 1) * 8;
    int bkb  = ((lane >> 3) & 1) * 8;

    float acc[4][NT8][4];
#pragma unroll
    for (int i = 0; i < 4; i++)
#pragma unroll
        for (int j = 0; j < NT8; j++)
#pragma unroll
            for (int q = 0; q < 4; q++) acc[i][j][q] = 0.f;

    int KC = p.K >> 5;

    auto load_stage = [&](int st, int k0) {
        uint32_t base = sb + (uint32_t)st * SS;
#pragma unroll 2
        for (int idx = tid; idx < 512; idx += 256) {
            int row = idx >> 2, c = idx & 3;
            uint32_t off = (uint32_t)(row * 64 + ((c * 16) ^ (((row >> 1) & 3) << 4)));
            CP16(base + off,        Ah + (size_t)row * p.lda + k0 + c * 8);
            CP16(base + 8192 + off, Al + (size_t)row * p.lda + k0 + c * 8);
        }
#pragma unroll 2
        for (int idx = tid; idx < TN * 4; idx += 256) {
            int row = idx >> 2, c = idx & 3;
            uint32_t off = (uint32_t)(row * 64 + ((c * 16) ^ (((row >> 1) & 3) << 4)));
            CP16(base + 16384 + off,           Bh + (size_t)row * p.ldb + k0 + c * 8);
            CP16(base + 16384 + TN * 64 + off, Bl + (size_t)row * p.ldb + k0 + c * 8);
        }
    };

    load_stage(0, 0);
    CP_COMMIT();

    for (int ch = 0; ch < KC; ch++) {
        if (ch + 1 < KC) {
            load_stage((ch + 1) & 1, (ch + 1) << 5);
            CP_COMMIT();
            CP_WAIT1();
        } else {
            CP_WAIT0();
        }
        __syncthreads();

        uint32_t base = sb + (uint32_t)(ch & 1) * SS;
        uint32_t aHiB = base, aLoB = base + 8192;
        uint32_t bHiB = base + 16384, bLoB = base + 16384 + TN * 64;

#pragma unroll
        for (int kk = 0; kk < 32; kk += 16) {
            uint32_t ah[4][4];
#pragma unroll
            for (int mt = 0; mt < 4; mt++)
                LDSM4(ah[mt], aHiB + soff(arow + mt * 16, kk + akb));
            uint32_t bh[NX4][4];
#pragma unroll
            for (int nx = 0; nx < NX4; nx++)
                LDSM4(bh[nx], bHiB + soff(brow + nx * 16, kk + bkb));
#pragma unroll
            for (int mt = 0; mt < 4; mt++)
#pragma unroll
                for (int nt = 0; nt < NT8; nt++)
                    MMA16816(acc[mt][nt], ah[mt], &bh[nt >> 1][(nt & 1) * 2]);

            uint32_t bl[NX4][4];
#pragma unroll
            for (int nx = 0; nx < NX4; nx++)
                LDSM4(bl[nx], bLoB + soff(brow + nx * 16, kk + bkb));
#pragma unroll
            for (int mt = 0; mt < 4; mt++)
#pragma unroll
                for (int nt = 0; nt < NT8; nt++)
                    MMA16816(acc[mt][nt], ah[mt], &bl[nt >> 1][(nt & 1) * 2]);

            uint32_t al[4][4];
#pragma unroll
            for (int mt = 0; mt < 4; mt++)
                LDSM4(al[mt], aLoB + soff(arow + mt * 16, kk + akb));
#pragma unroll
            for (int mt = 0; mt < 4; mt++)
#pragma unroll
                for (int nt = 0; nt < NT8; nt++)
                    MMA16816(acc[mt][nt], al[mt], &bh[nt >> 1][(nt & 1) * 2]);
        }
        __syncthreads();
    }

    // epilogue
    float alpha = p.alpha_vec ? p.alpha_vec[z >> p.alpha_shift] : 1.0f;
    int r0 = by * 128 + m0 + (lane >> 2);
    int c0 = bx * TN + n0 + (lane & 3) * 2;
#pragma unroll
    for (int mt = 0; mt < 4; mt++) {
#pragma unroll
        for (int nt = 0; nt < NT8; nt++) {
            int row = r0 + mt * 16;
            int col = c0 + nt * 8;
            float b0 = 0.f, b1 = 0.f;
            if (p.bias) { b0 = p.bias[col]; b1 = p.bias[col + 1]; }
            float v00 = acc[mt][nt][0] * alpha + b0;
            float v01 = acc[mt][nt][1] * alpha + b1;
            float v10 = acc[mt][nt][2] * alpha + b0;
            float v11 = acc[mt][nt][3] * alpha + b1;
            if (p.emode == 1) {
                rot_store(g_qr_h, g_qr_l, row, col, v00, v01, true);
                rot_store(g_qr_h, g_qr_l, row + 8, col, v10, v11, true);
            } else if (p.emode == 2) {
                rot_store(g_kr_h, g_kr_l, row, col, v00, v01, false);
                rot_store(g_kr_h, g_kr_l, row + 8, col, v10, v11, false);
            } else {
                if (p.C) {
                    *(float2*)(p.C + cbase + (size_t)row * p.ldc + col) = make_float2(v00, v01);
                    *(float2*)(p.C + cbase + (size_t)(row + 8) * p.ldc + col) = make_float2(v10, v11);
                }
                if (p.Ch) {
                    uint16_t h0, l0, h1, l1;
                    fsplit(v00, h0, l0); fsplit(v01, h1, l1);
                    *(uint32_t*)(p.Ch + cbase + (size_t)row * p.ldc + col) = (uint32_t)h0 | ((uint32_t)h1 << 16);
                    *(uint32_t*)(p.Cl + cbase + (size_t)row * p.ldc + col) = (uint32_t)l0 | ((uint32_t)l1 << 16);
                    fsplit(v10, h0, l0); fsplit(v11, h1, l1);
                    *(uint32_t*)(p.Ch + cbase + (size_t)(row + 8) * p.ldc + col) = (uint32_t)h0 | ((uint32_t)h1 << 16);
                    *(uint32_t*)(p.Cl + cbase + (size_t)(row + 8) * p.ldc + col) = (uint32_t)l0 | ((uint32_t)l1 << 16);
                }
            }
        }
    }
}

// ---------------- launch -----------------------------------------------------
#define SYM(var, sym) decltype(&sym[0]) var; cudaGetSymbolAddress((void**)&var, sym)

extern "C" void kernel_launch(void* const* d_in, const int* in_sizes, int n_in,
                              void* d_out, int out_size) {
    const float* x    = (const float*)d_in[0];
    const void*  mask = d_in[1];
    const float* dw_w = (const float*)d_in[3];
    const float* dw_b = (const float*)d_in[4];
    const float* pw_w = (const float*)d_in[5];
    const float* pw_b = (const float*)d_in[6];
    const float* w_kv = (const float*)d_in[7];
    const float* w_o  = (const float*)d_in[8];
    const float* b_o  = (const float*)d_in[9];
    float* out = (float*)d_out;

    const int SM128 = 2 * (16384 + 128 * 128);   // 65536
    const int SM64  = 2 * (16384 + 64 * 128);    // 49152
    cudaFuncSetAttribute(k_mma<128>, cudaFuncAttributeMaxDynamicSharedMemorySize, SM128);
    cudaFuncSetAttribute(k_mma<64>,  cudaFuncAttributeMaxDynamicSharedMemorySize, SM64);

    SYM(v_p, g_v);  SYM(dots_p, g_dots);
    SYM(xs_h, g_xs_h);    SYM(xs_l, g_xs_l);
    SYM(hdw_h, g_hdw_h);  SYM(hdw_l, g_hdw_l);
    SYM(pww_h, g_pww_h);  SYM(pww_l, g_pww_l);
    SYM(wkvT_h, g_wkvT_h); SYM(wkvT_l, g_wkvT_l);
    SYM(woT_h, g_woT_h);  SYM(woT_l, g_woT_l);
    SYM(qr_h, g_qr_h);    SYM(qr_l, g_qr_l);
    SYM(kr_h, g_kr_h);    SYM(kr_l, g_kr_l);
    SYM(attn_h, g_attn_h); SYM(attn_l, g_attn_l);
    SYM(vT_h, g_vT_h);    SYM(vT_l, g_vT_l);
    SYM(oi_h, g_oi_h);    SYM(oi_l, g_oi_l);
    SYM(alpha_p, g_alpha);

    k_detect<<<1, 256>>>((const unsigned char*)mask);
    k_norm_mask<<<(BN_TOT * NN + 255) / 256, 256>>>(mask);
    k_hasrows<<<BN_TOT, 256>>>();
    k_many<<<NB, NN>>>();
    k_trig<<<NN, 32>>>();

    k_split<<<(BN_TOT * NN * DIMC) / 256, 256>>>(x, xs_h, xs_l, BN_TOT * NN * DIMC);
    k_split<<<(INNERD * DIMC) / 256, 256>>>(pw_w, pww_h, pww_l, INNERD * DIMC);
    k_wkvT<<<(2 * INNERD * DIMC) / 256, 256>>>(w_kv);
    k_woT<<<(DIMC * INNERD) / 256, 256>>>(w_o);

    k_conv<<<BN_TOT * NN, DIMC>>>(x, dw_w, dw_b);

    // qproj + bias + rotary + has_rows -> qr split  (M=32768, N=512, K=256)
    {
        GemmP p = {hdw_h, hdw_l, DIMC, 0, pww_h, pww_l, DIMC, 0,
                   nullptr, nullptr, nullptr, 0, 0,
                   DIMC, pw_b, nullptr, 0, 0, 1};
        k_mma<128><<<dim3(4, 256, 1), 256, SM128>>>(p);
    }
    // K proj + rotary -> kr split  (M=32768, N=512, K=256; B = wkvT rows 0..511)
    {
        GemmP p = {xs_h, xs_l, DIMC, 0, wkvT_h, wkvT_l, DIMC, 0,
                   nullptr, nullptr, nullptr, 0, 0,
                   DIMC, nullptr, nullptr, 0, 0, 2};
        k_mma<128><<<dim3(4, 256, 1), 256, SM128>>>(p);
    }
    // V proj -> g_v fp32  (M=32768, N=512, K=256; B = wkvT rows 512..1023)
    {
        GemmP p = {xs_h, xs_l, DIMC, 0, wkvT_h + INNERD * DIMC, wkvT_l + INNERD * DIMC, DIMC, 0,
                   v_p, nullptr, nullptr, INNERD, 0,
                   DIMC, nullptr, nullptr, 0, 0, 0};
        k_mma<128><<<dim3(4, 256, 1), 256, SM128>>>(p);
    }
    k_vT<<<dim3(16, 16, BN_TOT), dim3(32, 8)>>>();
    // dots: 16 batches, M=N=512, K=2048 -> g_dots fp32 (alpha per b)
    {
        GemmP p = {qr_h, qr_l, 2048, (long long)NN * 2048, kr_h, kr_l, 2048, (long long)NN * 2048,
                   dots_p, nullptr, nullptr, NN, (long long)NN * NN,
                   2048, nullptr, alpha_p, 3, 0, 0};
        k_mma<128><<<dim3(4, 4, 16), 256, SM128>>>(p);
    }
    k_softmax<<<NB * HH * NN, 256>>>();
    // AV: 512 batches (bn,h), M=512, N=64, K=512 -> oi split
    {
        GemmP p = {attn_h, attn_l, NN, (long long)NN * NN, vT_h, vT_l, NN, (long long)DH * NN,
                   nullptr, oi_h, oi_l, INNERD, (long long)NN * INNERD,
                   NN, nullptr, nullptr, 0, 1, 0};
        k_mma<64><<<dim3(1, 4, BN_TOT * HH), 256, SM64>>>(p);
    }
    // final: M=32768, N=256, K=512 -> out fp32 (+bias)
    {
        GemmP p = {oi_h, oi_l, INNERD, 0, woT_h, woT_l, INNERD, 0,
                   out, nullptr, nullptr, DIMC, 0,
                   INNERD, b_o, nullptr, 0, 0, 0};
        k_mma<128><<<dim3(2, 256, 1), 256, SM128>>>(p);
    }
}